// round 17
// baseline (speedup 1.0000x reference)
#include <cuda_runtime.h>
#include <cuda_fp16.h>
#include <cstdint>
#include <cstddef>

#define DIM      1024
#define HEADS    16
#define HEAD_DIM 64
#define BLK      32
#define FEAT     128
#define BATCH    4
#define SEQ      4096
#define NBLK     (SEQ / BLK)      // 128
#define ROWS     (BATCH * SEQ)    // 16384

// Scratch (allocation-free rule: __device__ globals)
__device__ __half g_qkvh[(size_t)ROWS * 3 * DIM];            // 96 MB fp16
__device__ __half g_xh[(size_t)ROWS * DIM];                  // 32 MB
__device__ __half g_ah[(size_t)ROWS * DIM];                  // 32 MB
__device__ __half g_wqh[(size_t)3 * DIM * DIM];              // 6 MB
__device__ __half g_woh[(size_t)DIM * DIM];                  // 2 MB
__device__ __half g_pt[(size_t)HEADS * FEAT * HEAD_DIM];     // 256 KB projT [h][f][d]

// ---------------------------------------------------------------------------
// helpers
// ---------------------------------------------------------------------------
__device__ __forceinline__ uint32_t smem_u32(const void* p) {
    uint32_t a;
    asm("{ .reg .u64 t; cvta.to.shared.u64 t, %1; cvt.u32.u64 %0, t; }" : "=r"(a) : "l"(p));
    return a;
}

#define SW128(off) ((off) ^ (((off) >> 3) & 0x70))

#define CP16(dst, src) \
    asm volatile("cp.async.cg.shared.global [%0], [%1], 16;" :: "r"(dst), "l"(src) : "memory")
#define CP_COMMIT() asm volatile("cp.async.commit_group;" ::: "memory")
#define CP_WAIT1()  asm volatile("cp.async.wait_group 1;" ::: "memory")
#define CP_WAIT0()  asm volatile("cp.async.wait_group 0;" ::: "memory")

#define LDSM4(r0, r1, r2, r3, addr)                                           \
    asm volatile("ldmatrix.sync.aligned.m8n8.x4.shared.b16 {%0,%1,%2,%3}, [%4];" \
                 : "=r"(r0), "=r"(r1), "=r"(r2), "=r"(r3) : "r"(addr))

#define LDSM4T(r0, r1, r2, r3, addr)                                          \
    asm volatile("ldmatrix.sync.aligned.m8n8.x4.trans.shared.b16 {%0,%1,%2,%3}, [%4];" \
                 : "=r"(r0), "=r"(r1), "=r"(r2), "=r"(r3) : "r"(addr))

#define MMA_F16(d, a0, a1, a2, a3, b0, b1)                                    \
    asm volatile("mma.sync.aligned.m16n8k16.row.col.f32.f16.f16.f32 "         \
                 "{%0,%1,%2,%3}, {%4,%5,%6,%7}, {%8,%9}, {%0,%1,%2,%3};"      \
                 : "+f"((d)[0]), "+f"((d)[1]), "+f"((d)[2]), "+f"((d)[3])     \
                 : "r"(a0), "r"(a1), "r"(a2), "r"(a3), "r"(b0), "r"(b1))

__device__ __forceinline__ float elu1(float x) {
    return (x > 0.0f) ? (x + 1.0f) : __expf(x);
}

// ---------------------------------------------------------------------------
// fp16 mma.sync GEMM, 2 CTAs/SM, register double-buffered fragments:
// step s's MMAs overlap step s+1's LDSM (B ping-pong per step, A per k-step).
// ---------------------------------------------------------------------------
#define BM 128
#define BN 128
#define BKH 64
#define NSTAGE 3
#define TILE_B (BM * 128)
#define ST_BYTES (2 * TILE_B)
#define G_SMEM (NSTAGE * ST_BYTES) // 98304 B

template<bool BIAS, bool OUT16>
__global__ __launch_bounds__(256, 2)
void hgemm(const __half* __restrict__ Ah, const __half* __restrict__ Bh,
           const float* __restrict__ bias, float* __restrict__ Cf,
           __half* __restrict__ Ch, int M, int N, int K)
{
    extern __shared__ char smem[];
    const uint32_t sbase = smem_u32(smem);
    const int t = threadIdx.x;
    const int lid = t & 31, wid = t >> 5;
    const int wm = wid & 3, wn = wid >> 2;
    const int m0 = wm * 32, n0 = wn * 64;
    const int bn = blockIdx.x, bm = blockIdx.y;
    const int NK = K / BKH;

    const __half* Ahb = Ah + (size_t)bm * BM * K;
    const __half* Bhb = Bh + (size_t)bn * BN * K;

    const int prow = t >> 3;
    const int pch  = t & 7;

    auto load_stage = [&](int s, int kc) {
        const uint32_t sb0 = sbase + s * ST_BYTES;
        const int koff = kc * BKH;
#pragma unroll
        for (int i = 0; i < 4; i++) {
            int row = prow + i * 32;
            uint32_t off = SW128((uint32_t)(row * 128 + pch * 16));
            size_t g = (size_t)row * K + koff + pch * 8;
            CP16(sb0 + off,          Ahb + g);
            CP16(sb0 + TILE_B + off, Bhb + g);
        }
        CP_COMMIT();
    };

    const int lr = lid & 15;
    const int lk16 = (lid >> 4) * 16;
    const uint32_t aoff = (uint32_t)((m0 + lr) * 128 + lk16);
    uint32_t boff[4];
#pragma unroll
    for (int j = 0; j < 4; j++)
        boff[j] = (uint32_t)((n0 + 16 * j + lr) * 128 + lk16);

    float acc[2][8][4];
#pragma unroll
    for (int mi = 0; mi < 2; mi++)
#pragma unroll
        for (int f = 0; f < 8; f++)
#pragma unroll
            for (int r = 0; r < 4; r++) acc[mi][f][r] = 0.0f;

    load_stage(0, 0);
    load_stage(1, 1);

    for (int it = 0; it < NK; it++) {
        CP_WAIT1();
        __syncthreads();
        const int nxt = it + 2;
        if (nxt < NK) load_stage(nxt % NSTAGE, nxt);

        const uint32_t s0 = sbase + (it % NSTAGE) * ST_BYTES;
        const uint32_t sAh = s0;
        const uint32_t sBh = s0 + TILE_B;

        uint32_t afr[2][8], bfr[2][4];
        // preload first A pair + first B fragment
        LDSM4(afr[0][0], afr[0][1], afr[0][2], afr[0][3], sAh + SW128(aoff));
        LDSM4(afr[0][4], afr[0][5], afr[0][6], afr[0][7], sAh + SW128(aoff + 16 * 128));
        LDSM4(bfr[0][0], bfr[0][1], bfr[0][2], bfr[0][3], sBh + SW128(boff[0]));

#pragma unroll
        for (int ks = 0; ks < 4; ks++) {
            const int ab = ks & 1;
#pragma unroll
            for (int j = 0; j < 4; j++) {
                const int bb = (ks * 4 + j) & 1;
                // prefetch next step's fragments before issuing this step's MMAs
                if (j < 3) {
                    LDSM4(bfr[bb ^ 1][0], bfr[bb ^ 1][1], bfr[bb ^ 1][2], bfr[bb ^ 1][3],
                          sBh + SW128(boff[j + 1] + ks * 32));
                } else if (ks < 3) {
                    const uint32_t nkb = (ks + 1) * 32;
                    LDSM4(afr[ab ^ 1][0], afr[ab ^ 1][1], afr[ab ^ 1][2], afr[ab ^ 1][3],
                          sAh + SW128(aoff + nkb));
                    LDSM4(afr[ab ^ 1][4], afr[ab ^ 1][5], afr[ab ^ 1][6], afr[ab ^ 1][7],
                          sAh + SW128(aoff + 16 * 128 + nkb));
                    LDSM4(bfr[bb ^ 1][0], bfr[bb ^ 1][1], bfr[bb ^ 1][2], bfr[bb ^ 1][3],
                          sBh + SW128(boff[0] + nkb));
                }
                MMA_F16(acc[0][2 * j + 0], afr[ab][0], afr[ab][1], afr[ab][2], afr[ab][3],
                        bfr[bb][0], bfr[bb][2]);
                MMA_F16(acc[0][2 * j + 1], afr[ab][0], afr[ab][1], afr[ab][2], afr[ab][3],
                        bfr[bb][1], bfr[bb][3]);
                MMA_F16(acc[1][2 * j + 0], afr[ab][4], afr[ab][5], afr[ab][6], afr[ab][7],
                        bfr[bb][0], bfr[bb][2]);
                MMA_F16(acc[1][2 * j + 1], afr[ab][4], afr[ab][5], afr[ab][6], afr[ab][7],
                        bfr[bb][1], bfr[bb][3]);
            }
        }
    }

    const int g = lid >> 2, tq = lid & 3;
#pragma unroll
    for (int mi = 0; mi < 2; mi++) {
        int rowl = m0 + mi * 16 + g;
#pragma unroll
        for (int f = 0; f < 8; f++) {
            int col = n0 + f * 8 + tq * 2;
            if (OUT16) {
                __half* p0 = Ch + (size_t)(bm * BM + rowl) * N + bn * BN + col;
                __half* p1 = Ch + (size_t)(bm * BM + rowl + 8) * N + bn * BN + col;
                *(__half2*)p0 = __floats2half2_rn(acc[mi][f][0], acc[mi][f][1]);
                *(__half2*)p1 = __floats2half2_rn(acc[mi][f][2], acc[mi][f][3]);
            } else {
                float b0 = 0.0f, b1 = 0.0f;
                if (BIAS) { b0 = bias[bn * BN + col]; b1 = bias[bn * BN + col + 1]; }
                float* p0 = Cf + (size_t)(bm * BM + rowl) * N + bn * BN + col;
                float* p1 = Cf + (size_t)(bm * BM + rowl + 8) * N + bn * BN + col;
                float2 v0 = { acc[mi][f][0] + b0, acc[mi][f][1] + b1 };
                float2 v1 = { acc[mi][f][2] + b0, acc[mi][f][3] + b1 };
                *(float2*)p0 = v0;
                *(float2*)p1 = v1;
            }
        }
    }
}

// ---------------------------------------------------------------------------
// fused_attn: per (b*h, 64-token tile), 2 CTAs/SM (unchanged structure from
// R16 except z is computed by all 8 warps with shfl-reduce).
// ---------------------------------------------------------------------------
#define TOK 64
#define KFB 272
#define VB  144
#define KVB 144
#define FS_Q    0
#define FS_K    8192
#define FS_B    16384
#define FS_KV   0                        // alias over staging
#define FS_QF   32768
#define FS_KF   (FS_QF + TOK * KFB)      // 50176
#define FS_V    (FS_KF + TOK * KFB)      // 67584
#define FS_KSUM (FS_V + TOK * VB)        // 76800
#define FS_Z    (FS_KSUM + 512)          // 77312
#define FS_SMEM (FS_Z + 128)             // 77440

__global__ __launch_bounds__(256, 2)
void fused_attn(const __half* __restrict__ qkvh, const __half* __restrict__ pt,
                __half* __restrict__ attn_h)
{
    extern __shared__ char sm[];
    const uint32_t sb = smem_u32(sm);
    const int t = threadIdx.x;
    const int lid = t & 31, wid = t >> 5;
    const int bh = blockIdx.x, nt = blockIdx.y;
    const int b = bh / HEADS, h = bh - b * HEADS;
    const size_t rowbase = (size_t)b * SEQ + nt * TOK;

    // ---- stage q, k (64x128B SW128), v (144B rows), projT ----
    {
        int r = t >> 2, c2 = (t & 3) * 2;
        const __half* qrow = qkvh + (rowbase + r) * (3 * DIM) + h * HEAD_DIM;
        const __half* krow = qrow + DIM;
        const __half* vrow = qrow + 2 * DIM;
#pragma unroll
        for (int cc = 0; cc < 2; cc++) {
            int c = c2 + cc;
            uint32_t qk = SW128((uint32_t)(r * 128 + c * 16));
            CP16(sb + FS_Q + qk, qrow + c * 8);
            CP16(sb + FS_K + qk, krow + c * 8);
            CP16(sb + FS_V + (uint32_t)(r * VB + c * 16), vrow + c * 8);
        }
        int pr = t >> 1, ph = t & 1;
        const __half* brow = pt + (size_t)h * FEAT * HEAD_DIM + pr * 64 + ph * 32;
#pragma unroll
        for (int c = 0; c < 4; c++) {
            uint32_t off = SW128((uint32_t)(pr * 128 + ph * 64 + c * 16));
            CP16(sb + FS_B + off, brow + c * 8);
        }
        CP_COMMIT();
    }
    CP_WAIT0();
    __syncthreads();

    // ---- feat: qf/kf = elu([64,64] @ projT^T)+1 -> smem padded rows ----
    {
        const int wm = wid & 1, wn = wid >> 1;
        const int m0 = wm * 32, n0 = wn * 32;
        const int lr = lid & 15;
        const int lk16 = (lid >> 4) * 16;
        const uint32_t aoff = (uint32_t)((m0 + lr) * 128 + lk16);
        uint32_t boff[2];
#pragma unroll
        for (int j = 0; j < 2; j++)
            boff[j] = (uint32_t)((n0 + 16 * j + lr) * 128 + lk16);
        const int g = lid >> 2, tq = lid & 3;

#pragma unroll
        for (int op = 0; op < 2; op++) {
            const uint32_t sA = sb + (op ? FS_K : FS_Q);
            float acc[2][4][4];
#pragma unroll
            for (int mi = 0; mi < 2; mi++)
#pragma unroll
                for (int f = 0; f < 4; f++)
#pragma unroll
                    for (int r = 0; r < 4; r++) acc[mi][f][r] = 0.0f;

#pragma unroll
            for (int ks = 0; ks < 4; ks++) {
                const uint32_t kb = ks * 32;
                uint32_t a0[4], a1[4];
                LDSM4(a0[0], a0[1], a0[2], a0[3], sA + SW128(aoff + kb));
                LDSM4(a1[0], a1[1], a1[2], a1[3], sA + SW128(aoff + 16 * 128 + kb));
#pragma unroll
                for (int j = 0; j < 2; j++) {
                    uint32_t bfr[4];
                    LDSM4(bfr[0], bfr[1], bfr[2], bfr[3], sb + FS_B + SW128(boff[j] + kb));
                    MMA_F16(acc[0][2 * j + 0], a0[0], a0[1], a0[2], a0[3], bfr[0], bfr[2]);
                    MMA_F16(acc[0][2 * j + 1], a0[0], a0[1], a0[2], a0[3], bfr[1], bfr[3]);
                    MMA_F16(acc[1][2 * j + 0], a1[0], a1[1], a1[2], a1[3], bfr[0], bfr[2]);
                    MMA_F16(acc[1][2 * j + 1], a1[0], a1[1], a1[2], a1[3], bfr[1], bfr[3]);
                }
            }

            char* dst = sm + (op ? FS_KF : FS_QF);
#pragma unroll
            for (int mi = 0; mi < 2; mi++) {
                int rowl = m0 + mi * 16 + g;
#pragma unroll
                for (int f = 0; f < 4; f++) {
                    int col = n0 + f * 8 + tq * 2;
                    *(__half2*)(dst + rowl * KFB + col * 2) =
                        __floats2half2_rn(elu1(acc[mi][f][0]), elu1(acc[mi][f][1]));
                    *(__half2*)(dst + (rowl + 8) * KFB + col * 2) =
                        __floats2half2_rn(elu1(acc[mi][f][2]), elu1(acc[mi][f][3]));
                }
            }
        }
    }
    __syncthreads();

    // ---- per 32-token block: kv (HMMA), ksum/z (fp32), out (HMMA) ----
    const int f0 = wid * 16;
    const int trow = (lid & 7) + ((lid >> 4) & 1) * 8;
    const int tcol8 = ((lid >> 3) & 1) * 8;
    const int wm2 = wid & 1, wn2 = wid >> 1;
    const int s0 = wm2 * 16, d0 = wn2 * 16;
    const int g = lid >> 2, tq = lid & 3;

    for (int m2 = 0; m2 < 2; m2++) {
        const int sr = m2 * 32;

        // ksum (t<128) + MMA1 accumulate (regs only)
        float ks_acc = 0.0f;
        if (t < FEAT) {
            for (int s = 0; s < BLK; s++)
                ks_acc += __half2float(*(const __half*)(sm + FS_KF + (sr + s) * KFB + t * 2));
        }
        float acc1[8][4];
#pragma unroll
        for (int j = 0; j < 8; j++)
#pragma unroll
            for (int r = 0; r < 4; r++) acc1[j][r] = 0.0f;

#pragma unroll
        for (int ksi = 0; ksi < 2; ksi++) {
            uint32_t a[4];
            LDSM4T(a[0], a[1], a[2], a[3],
                   sb + FS_KF + (uint32_t)((sr + trow + ksi * 16) * KFB + (f0 + tcol8) * 2));
#pragma unroll
            for (int nj = 0; nj < 4; nj++) {
                uint32_t bf[4];
                LDSM4T(bf[0], bf[1], bf[2], bf[3],
                       sb + FS_V + (uint32_t)((sr + trow + ksi * 16) * VB + (nj * 16 + tcol8) * 2));
                MMA_F16(acc1[2 * nj + 0], a[0], a[1], a[2], a[3], bf[0], bf[2]);
                MMA_F16(acc1[2 * nj + 1], a[0], a[1], a[2], a[3], bf[1], bf[3]);
            }
        }

        // write kv + ksum
        if (t < FEAT) *(float*)(sm + FS_KSUM + t * 4) = ks_acc;
#pragma unroll
        for (int j = 0; j < 8; j++) {
            int dd = j * 8 + tq * 2;
            *(__half2*)(sm + FS_KV + (f0 + g) * KVB + dd * 2) =
                __floats2half2_rn(acc1[j][0], acc1[j][1]);
            *(__half2*)(sm + FS_KV + (f0 + g + 8) * KVB + dd * 2) =
                __floats2half2_rn(acc1[j][2], acc1[j][3]);
        }
        __syncthreads();

        // z: all 8 warps, 4 rows each, 8 lanes per row, shfl reduce
        {
            const int rl = lid >> 3;          // 0..3
            const int fg = lid & 7;           // f-group of 16
            const int srow = wid * 4 + rl;    // 0..31 local
            const char* qrow = sm + FS_QF + (sr + srow) * KFB + fg * 32;
            const float* ksp = (const float*)(sm + FS_KSUM) + fg * 16;
            float za = 0.0f;
#pragma unroll
            for (int i = 0; i < 8; i++) {
                float2 q = __half22float2(*(const __half2*)(qrow + i * 4));
                za += q.x * ksp[2 * i] + q.y * ksp[2 * i + 1];
            }
            za += __shfl_xor_sync(0xffffffff, za, 1);
            za += __shfl_xor_sync(0xffffffff, za, 2);
            za += __shfl_xor_sync(0xffffffff, za, 4);
            if (fg == 0)
                *(float*)(sm + FS_Z + srow * 4) = 1.0f / (za + 1e-8f);
        }

        float acc2[2][4];
#pragma unroll
        for (int j = 0; j < 2; j++)
#pragma unroll
            for (int r = 0; r < 4; r++) acc2[j][r] = 0.0f;

        const uint32_t qoff = (uint32_t)(FS_QF + (sr + s0 + (lid & 15)) * KFB + (lid >> 4) * 16);
#pragma unroll
        for (int ksi = 0; ksi < 8; ksi++) {
            uint32_t a[4];
            LDSM4(a[0], a[1], a[2], a[3], sb + qoff + ksi * 32);
            uint32_t bf[4];
            LDSM4T(bf[0], bf[1], bf[2], bf[3],
                   sb + FS_KV + (uint32_t)((ksi * 16 + trow) * KVB + (d0 + tcol8) * 2));
            MMA_F16(acc2[0], a[0], a[1], a[2], a[3], bf[0], bf[2]);
            MMA_F16(acc2[1], a[0], a[1], a[2], a[3], bf[1], bf[3]);
        }
        __syncthreads();

        // epilogue: scale by z, write fp16 attn
#pragma unroll
        for (int half = 0; half < 2; half++) {
            int s = s0 + g + half * 8;
            float z = *(const float*)(sm + FS_Z + s * 4);
            size_t off = (rowbase + sr + s) * DIM + h * HEAD_DIM;
            *(__half2*)(attn_h + off + d0 + tq * 2) =
                __floats2half2_rn(acc2[0][2 * half] * z, acc2[0][2 * half + 1] * z);
            *(__half2*)(attn_h + off + d0 + 8 + tq * 2) =
                __floats2half2_rn(acc2[1][2 * half] * z, acc2[1][2 * half + 1] * z);
        }
    }
}

// ---------------------------------------------------------------------------
// prep kernels
// ---------------------------------------------------------------------------
__global__ void round_kernel(const float* __restrict__ in, __half* __restrict__ h,
                             int n4)
{
    int i = blockIdx.x * blockDim.x + threadIdx.x;
    if (i >= n4) return;
    float4 v = ((const float4*)in)[i];
    ((__half2*)h)[2 * i]     = __halves2half2(__float2half_rn(v.x), __float2half_rn(v.y));
    ((__half2*)h)[2 * i + 1] = __halves2half2(__float2half_rn(v.z), __float2half_rn(v.w));
}

__global__ void transpose_h(const float* __restrict__ in,
                            __half* __restrict__ oh, int R, int C)
{
    __shared__ float tile[32][33];
    int bx = blockIdx.x * 32, by = blockIdx.y * 32;
#pragma unroll
    for (int i = 0; i < 32; i += 8)
        tile[threadIdx.y + i][threadIdx.x] =
            in[(size_t)(by + threadIdx.y + i) * C + bx + threadIdx.x];
    __syncthreads();
#pragma unroll
    for (int i = 0; i < 32; i += 8) {
        size_t idx = (size_t)(bx + threadIdx.y + i) * R + by + threadIdx.x;
        oh[idx] = __float2half_rn(tile[threadIdx.x][threadIdx.y + i]);
    }
}

__global__ void transpose_ph(const float* __restrict__ in, __half* __restrict__ out)
{
    __shared__ float tile[32][33];
    int hh = blockIdx.z;
    int bx = blockIdx.x * 32;
    int by = blockIdx.y * 32;
    const float* src = in + (size_t)hh * HEAD_DIM * FEAT;
    __half* dst = out + (size_t)hh * FEAT * HEAD_DIM;
#pragma unroll
    for (int i = 0; i < 32; i += 8)
        tile[threadIdx.y + i][threadIdx.x] =
            src[(size_t)(by + threadIdx.y + i) * FEAT + bx + threadIdx.x];
    __syncthreads();
#pragma unroll
    for (int i = 0; i < 32; i += 8)
        dst[(size_t)(bx + threadIdx.y + i) * HEAD_DIM + by + threadIdx.x] =
            __float2half_rn(tile[threadIdx.x][threadIdx.y + i]);
}

// ---------------------------------------------------------------------------
extern "C" void kernel_launch(void* const* d_in, const int* in_sizes, int n_in,
                              void* d_out, int out_size)
{
    const float* x    = (const float*)d_in[0];
    const float* Wqkv = (const float*)d_in[1];
    const float* proj = (const float*)d_in[2];
    const float* Wout = (const float*)d_in[3];
    const float* bout = (const float*)d_in[4];
    float* out = (float*)d_out;

    __half *qkvh, *xh, *ah, *wqh, *woh, *pt;
    cudaGetSymbolAddress((void**)&qkvh, g_qkvh);
    cudaGetSymbolAddress((void**)&xh,   g_xh);
    cudaGetSymbolAddress((void**)&ah,   g_ah);
    cudaGetSymbolAddress((void**)&wqh,  g_wqh);
    cudaGetSymbolAddress((void**)&woh,  g_woh);
    cudaGetSymbolAddress((void**)&pt,   g_pt);

    cudaFuncSetAttribute((const void*)hgemm<false, true>,
                         cudaFuncAttributeMaxDynamicSharedMemorySize, G_SMEM);
    cudaFuncSetAttribute((const void*)hgemm<true, false>,
                         cudaFuncAttributeMaxDynamicSharedMemorySize, G_SMEM);
    cudaFuncSetAttribute((const void*)fused_attn,
                         cudaFuncAttributeMaxDynamicSharedMemorySize, FS_SMEM);

    // 0) operand prep
    {
        int n4 = ROWS * DIM / 4;
        round_kernel<<<(n4 + 255) / 256, 256>>>(x, xh, n4);
    }
    transpose_h<<<dim3((3 * DIM) / 32, DIM / 32), dim3(32, 8)>>>(Wqkv, wqh, DIM, 3 * DIM);
    transpose_h<<<dim3(DIM / 32, DIM / 32), dim3(32, 8)>>>(Wout, woh, DIM, DIM);
    transpose_ph<<<dim3(FEAT / 32, HEAD_DIM / 32, HEADS), dim3(32, 8)>>>(proj, pt);

    // 1) qkvh = fp16(x @ Wqkv)
    hgemm<false, true><<<dim3((3 * DIM) / BN, ROWS / BM), 256, G_SMEM>>>(
        xh, wqh, nullptr, nullptr, qkvh, ROWS, 3 * DIM, DIM);

    // 2) fused feature + block linear attention (64-token tiles, 2 CTAs/SM)
    fused_attn<<<dim3(BATCH * HEADS, SEQ / TOK), 256, FS_SMEM>>>(qkvh, pt, ah);

    // 3) out = attn @ Wout + bout
    hgemm<true, false><<<dim3(DIM / BN, ROWS / BM), 256, G_SMEM>>>(
        ah, woh, bout, out, nullptr, ROWS, DIM, DIM);
}